// round 3
// baseline (speedup 1.0000x reference)
#include <cuda_runtime.h>
#include <cuda_bf16.h>
#include <cstdint>

#define N_NODES    50000
#define N_EDGES    800000
#define HIDDEN     128
#define NUM_GRAPHS 512

// ---------------- scratch (static device globals; no allocation) ----------------
__device__ float4 g_bufA[N_NODES * 32];     // 50000 x 128 floats
__device__ float4 g_bufB[N_NODES * 32];
__device__ int    g_deg[N_NODES];
__device__ int    g_rowptr[N_NODES + 1];
__device__ int    g_cursor[N_NODES];
__device__ int    g_col[N_EDGES];
__device__ float  g_pool[NUM_GRAPHS * HIDDEN];
__device__ float  g_cnt[NUM_GRAPHS];

// ---------------- zero scratch ----------------
__global__ void zero_kernel() {
    int i = blockIdx.x * blockDim.x + threadIdx.x;
    int stride = gridDim.x * blockDim.x;
    for (int j = i; j < N_NODES; j += stride) g_deg[j] = 0;
    for (int j = i; j < NUM_GRAPHS * HIDDEN; j += stride) g_pool[j] = 0.0f;
    for (int j = i; j < NUM_GRAPHS; j += stride) g_cnt[j] = 0.0f;
}

// ---------------- degree histogram over dst (edge_index is int32: JAX x64 disabled) ----
__global__ void hist_kernel(const int* __restrict__ ei) {
    int e = blockIdx.x * blockDim.x + threadIdx.x;
    if (e < N_EDGES) {
        int dst = ei[N_EDGES + e];
        if ((unsigned)dst < (unsigned)N_NODES) atomicAdd(&g_deg[dst], 1);
    }
}

// ---------------- exclusive scan (single block, warp-shuffle based) ----------------
__global__ void scan_kernel() {
    __shared__ int warp_sums[32];
    __shared__ int s_carry;
    int tid = threadIdx.x, lane = tid & 31, w = tid >> 5;
    if (tid == 0) { s_carry = 0; g_rowptr[0] = 0; }
    __syncthreads();
    for (int base = 0; base < N_NODES; base += 1024) {
        int i = base + tid;
        int v = (i < N_NODES) ? g_deg[i] : 0;
        int inc = v;
        #pragma unroll
        for (int o = 1; o < 32; o <<= 1) {
            int t = __shfl_up_sync(0xFFFFFFFFu, inc, o);
            if (lane >= o) inc += t;
        }
        if (lane == 31) warp_sums[w] = inc;
        __syncthreads();
        if (w == 0) {
            int s = warp_sums[lane];
            int si = s;
            #pragma unroll
            for (int o = 1; o < 32; o <<= 1) {
                int t = __shfl_up_sync(0xFFFFFFFFu, si, o);
                if (lane >= o) si += t;
            }
            warp_sums[lane] = si - s;   // exclusive offsets of warp totals
        }
        __syncthreads();
        int carry = s_carry;
        int incl = inc + warp_sums[w] + carry;
        if (i < N_NODES) {
            g_rowptr[i + 1] = incl;
            g_cursor[i]     = incl - v;
        }
        __syncthreads();
        if (tid == 1023) s_carry = incl;
        __syncthreads();
    }
}

// ---------------- CSR fill ----------------
__global__ void fill_kernel(const int* __restrict__ ei) {
    int e = blockIdx.x * blockDim.x + threadIdx.x;
    if (e < N_EDGES) {
        int src = ei[e];
        int dst = ei[N_EDGES + e];
        if ((unsigned)dst < (unsigned)N_NODES && (unsigned)src < (unsigned)N_NODES) {
            int pos = atomicAdd(&g_cursor[dst], 1);
            g_col[pos] = src;
        }
    }
}

// ---------------- aggregation: out[i] = in[i] + sum_{j in N(i)} in[j] ----------------
// warp per node, float4 per lane (128 floats / 32 lanes)
__global__ void agg_kernel(const float4* __restrict__ in, float4* __restrict__ out) {
    int gw = (blockIdx.x * blockDim.x + threadIdx.x) >> 5;
    if (gw >= N_NODES) return;
    int lane = threadIdx.x & 31;
    float4 acc = in[gw * 32 + lane];
    int s = g_rowptr[gw], e = g_rowptr[gw + 1];
    int j = (s < e) ? g_col[s] : 0;
    for (int p = s; p < e; p++) {
        int jn = (p + 1 < e) ? g_col[p + 1] : 0;   // prefetch next index
        float4 v = in[j * 32 + lane];
        acc.x += v.x; acc.y += v.y; acc.z += v.z; acc.w += v.w;
        j = jn;
    }
    out[gw * 32 + lane] = acc;
}

// ---------------- GEMM: C = relu(A[nrows,128] @ W[128,128] + b) ----------------
// block: 64 rows x 128 cols, 256 threads; thread: 8 rows x 4 cols.
// smem: full W (64KB) + A tile (32KB) = 96KB dynamic.
__global__ __launch_bounds__(256) void gemm_relu_kernel(
    const float* __restrict__ A, const float* __restrict__ W,
    const float* __restrict__ bias, float* __restrict__ C, int nrows)
{
    extern __shared__ float sh[];
    float* sW = sh;                 // 128*128
    float* sA = sh + 128 * 128;     // 64*128
    int tid = threadIdx.x;
    int row0 = blockIdx.x * 64;

    const float4* W4 = (const float4*)W;
    float4* sW4 = (float4*)sW;
    #pragma unroll
    for (int i = 0; i < 16; i++) sW4[tid + i * 256] = W4[tid + i * 256];

    int nr = min(64, nrows - row0);
    const float4* A4 = (const float4*)(A + (size_t)row0 * 128);
    float4* sA4 = (float4*)sA;
    for (int i = tid; i < nr * 32; i += 256) sA4[i] = A4[i];
    __syncthreads();

    int cg = tid & 31;   // cols cg*4 .. cg*4+3
    int rg = tid >> 5;   // rows rg*8 .. rg*8+7

    float acc[8][4];
    float4 bv = ((const float4*)bias)[cg];
    #pragma unroll
    for (int p = 0; p < 8; p++) {
        acc[p][0] = bv.x; acc[p][1] = bv.y; acc[p][2] = bv.z; acc[p][3] = bv.w;
    }

    const float* sArow = sA + rg * 8 * 128;
    #pragma unroll 4
    for (int k = 0; k < 128; k++) {
        float4 w4 = sW4[k * 32 + cg];
        #pragma unroll
        for (int p = 0; p < 8; p++) {
            float a = sArow[p * 128 + k];   // broadcast across warp (same rg)
            acc[p][0] += a * w4.x;
            acc[p][1] += a * w4.y;
            acc[p][2] += a * w4.z;
            acc[p][3] += a * w4.w;
        }
    }

    float4* C4 = (float4*)(C + (size_t)row0 * 128);
    #pragma unroll
    for (int p = 0; p < 8; p++) {
        int r = rg * 8 + p;
        if (r < nr) {
            float4 o;
            o.x = fmaxf(acc[p][0], 0.0f);
            o.y = fmaxf(acc[p][1], 0.0f);
            o.z = fmaxf(acc[p][2], 0.0f);
            o.w = fmaxf(acc[p][3], 0.0f);
            C4[r * 32 + cg] = o;
        }
    }
}

// ---------------- mean-pool accumulation (batch is int32) ----------------
__global__ void pool_kernel(const float4* __restrict__ h, const int* __restrict__ batch) {
    int gw = (blockIdx.x * blockDim.x + threadIdx.x) >> 5;
    if (gw >= N_NODES) return;
    int lane = threadIdx.x & 31;
    int g = batch[gw];
    if ((unsigned)g >= (unsigned)NUM_GRAPHS) return;
    float4 v = h[gw * 32 + lane];
    float* base = &g_pool[g * HIDDEN + lane * 4];
    atomicAdd(base + 0, v.x);
    atomicAdd(base + 1, v.y);
    atomicAdd(base + 2, v.z);
    atomicAdd(base + 3, v.w);
    if (lane == 0) atomicAdd(&g_cnt[g], 1.0f);
}

// ---------------- final FC: out[g] = (pool[g]/cnt[g]) @ Wfc + bfc ----------------
__global__ void fc_kernel(const float* __restrict__ Wfc, const float* __restrict__ bfc,
                          float* __restrict__ out) {
    int g = blockIdx.x * blockDim.x + threadIdx.x;
    if (g >= NUM_GRAPHS) return;
    float inv = 1.0f / fmaxf(g_cnt[g], 1.0f);
    float a0 = 0.0f, a1 = 0.0f;
    const float* row = &g_pool[g * HIDDEN];
    #pragma unroll 4
    for (int k = 0; k < HIDDEN; k++) {
        float v = row[k];
        a0 += v * Wfc[k * 2 + 0];
        a1 += v * Wfc[k * 2 + 1];
    }
    out[g * 2 + 0] = a0 * inv + bfc[0];
    out[g * 2 + 1] = a1 * inv + bfc[1];
}

// ---------------- launch ----------------
extern "C" void kernel_launch(void* const* d_in, const int* in_sizes, int n_in,
                              void* d_out, int out_size) {
    // Robust input binding by element count (same-size inputs keep dict order):
    // x:6400000  edge_index:1600000  batch:50000  W(4x):16384  b(4x):128  Wfc:256  bfc:2
    const float* x = nullptr;
    const int* ei = nullptr;
    const int* batch = nullptr;
    const float* Ws[4] = {nullptr, nullptr, nullptr, nullptr};
    const float* bs[4] = {nullptr, nullptr, nullptr, nullptr};
    const float* Wfc = nullptr;
    const float* bfc = nullptr;
    int wi = 0, bi = 0;
    for (int i = 0; i < n_in; i++) {
        int sz = in_sizes[i];
        if      (sz == N_NODES * HIDDEN)   x     = (const float*)d_in[i];
        else if (sz == 2 * N_EDGES)        ei    = (const int*)d_in[i];
        else if (sz == N_NODES)            batch = (const int*)d_in[i];
        else if (sz == HIDDEN * HIDDEN)    { if (wi < 4) Ws[wi++] = (const float*)d_in[i]; }
        else if (sz == HIDDEN)             { if (bi < 4) bs[bi++] = (const float*)d_in[i]; }
        else if (sz == HIDDEN * 2)         Wfc   = (const float*)d_in[i];
        else if (sz == 2)                  bfc   = (const float*)d_in[i];
    }
    float* out = (float*)d_out;

    float4* bufA; float4* bufB;
    cudaGetSymbolAddress((void**)&bufA, g_bufA);
    cudaGetSymbolAddress((void**)&bufB, g_bufB);

    const int SMEM = (128 * 128 + 64 * 128) * sizeof(float);   // 96 KB
    cudaFuncSetAttribute(gemm_relu_kernel, cudaFuncAttributeMaxDynamicSharedMemorySize, SMEM);

    // CSR build
    zero_kernel<<<256, 256>>>();
    hist_kernel<<<(N_EDGES + 255) / 256, 256>>>(ei);
    scan_kernel<<<1, 1024>>>();
    fill_kernel<<<(N_EDGES + 255) / 256, 256>>>(ei);

    int agg_blocks = (N_NODES * 32 + 255) / 256;
    int gemm_blocks = (N_NODES + 63) / 64;

    // Layer 1
    agg_kernel<<<agg_blocks, 256>>>((const float4*)x, bufA);
    gemm_relu_kernel<<<gemm_blocks, 256, SMEM>>>((const float*)bufA, Ws[0], bs[0], (float*)bufB, N_NODES);
    gemm_relu_kernel<<<gemm_blocks, 256, SMEM>>>((const float*)bufB, Ws[1], bs[1], (float*)bufA, N_NODES);

    // Layer 2
    agg_kernel<<<agg_blocks, 256>>>(bufA, bufB);
    gemm_relu_kernel<<<gemm_blocks, 256, SMEM>>>((const float*)bufB, Ws[2], bs[2], (float*)bufA, N_NODES);
    gemm_relu_kernel<<<gemm_blocks, 256, SMEM>>>((const float*)bufA, Ws[3], bs[3], (float*)bufB, N_NODES);

    // Pool + FC
    pool_kernel<<<agg_blocks, 256>>>(bufB, batch);
    fc_kernel<<<(NUM_GRAPHS + 255) / 256, 256>>>(Wfc, bfc, out);
}

// round 5
// speedup vs baseline: 1.3886x; 1.3886x over previous
#include <cuda_runtime.h>
#include <cuda_bf16.h>
#include <cstdint>

#define N_NODES    50000
#define N_EDGES    800000
#define HIDDEN     128
#define NUM_GRAPHS 512

// ================= scratch (static device globals; no allocation) =================
__device__ __nv_bfloat16 g_Ahi[N_NODES * HIDDEN];
__device__ __nv_bfloat16 g_Alo[N_NODES * HIDDEN];
__device__ __nv_bfloat16 g_Mhi[N_NODES * HIDDEN];
__device__ __nv_bfloat16 g_Mlo[N_NODES * HIDDEN];
__device__ float         g_H[N_NODES * HIDDEN];
__device__ __nv_bfloat16 g_Whi[4][HIDDEN * HIDDEN];   // transposed: [n][k]
__device__ __nv_bfloat16 g_Wlo[4][HIDDEN * HIDDEN];
__device__ int    g_deg[N_NODES];
__device__ int    g_rowptr[N_NODES + 1];
__device__ int    g_cursor[N_NODES];
__device__ int    g_col[N_EDGES];
__device__ float  g_pool[NUM_GRAPHS * HIDDEN];

// ================= CSR build =================
__global__ void zero_kernel() {
    int i = blockIdx.x * blockDim.x + threadIdx.x;
    int stride = gridDim.x * blockDim.x;
    for (int j = i; j < N_NODES; j += stride) g_deg[j] = 0;
    for (int j = i; j < NUM_GRAPHS * HIDDEN; j += stride) g_pool[j] = 0.0f;
}
__global__ void hist_kernel(const int* __restrict__ ei) {
    int e = blockIdx.x * blockDim.x + threadIdx.x;
    if (e < N_EDGES) {
        int dst = ei[N_EDGES + e];
        if ((unsigned)dst < (unsigned)N_NODES) atomicAdd(&g_deg[dst], 1);
    }
}
__global__ void scan_kernel() {
    __shared__ int warp_sums[32];
    __shared__ int s_carry;
    int tid = threadIdx.x, lane = tid & 31, w = tid >> 5;
    if (tid == 0) { s_carry = 0; g_rowptr[0] = 0; }
    __syncthreads();
    for (int base = 0; base < N_NODES; base += 1024) {
        int i = base + tid;
        int v = (i < N_NODES) ? g_deg[i] : 0;
        int inc = v;
        #pragma unroll
        for (int o = 1; o < 32; o <<= 1) {
            int t = __shfl_up_sync(0xFFFFFFFFu, inc, o);
            if (lane >= o) inc += t;
        }
        if (lane == 31) warp_sums[w] = inc;
        __syncthreads();
        if (w == 0) {
            int s = warp_sums[lane];
            int si = s;
            #pragma unroll
            for (int o = 1; o < 32; o <<= 1) {
                int t = __shfl_up_sync(0xFFFFFFFFu, si, o);
                if (lane >= o) si += t;
            }
            warp_sums[lane] = si - s;
        }
        __syncthreads();
        int carry = s_carry;
        int incl = inc + warp_sums[w] + carry;
        if (i < N_NODES) {
            g_rowptr[i + 1] = incl;
            g_cursor[i]     = incl - v;
        }
        __syncthreads();
        if (tid == 1023) s_carry = incl;
        __syncthreads();
    }
}
__global__ void fill_kernel(const int* __restrict__ ei) {
    int e = blockIdx.x * blockDim.x + threadIdx.x;
    if (e < N_EDGES) {
        int src = ei[e];
        int dst = ei[N_EDGES + e];
        if ((unsigned)dst < (unsigned)N_NODES && (unsigned)src < (unsigned)N_NODES) {
            int pos = atomicAdd(&g_cursor[dst], 1);
            g_col[pos] = src;
        }
    }
}

// ================= aggregation + split-bf16 conversion =================
__global__ void agg_conv_kernel(const float4* __restrict__ in,
                                __nv_bfloat16* __restrict__ Ohi,
                                __nv_bfloat16* __restrict__ Olo) {
    int gw = (blockIdx.x * blockDim.x + threadIdx.x) >> 5;
    if (gw >= N_NODES) return;
    int lane = threadIdx.x & 31;
    float4 acc = in[gw * 32 + lane];
    int s = g_rowptr[gw], e = g_rowptr[gw + 1];
    int j = (s < e) ? g_col[s] : 0;
    for (int p = s; p < e; p++) {
        int jn = (p + 1 < e) ? g_col[p + 1] : 0;
        float4 v = in[j * 32 + lane];
        acc.x += v.x; acc.y += v.y; acc.z += v.z; acc.w += v.w;
        j = jn;
    }
    __nv_bfloat16 hx = __float2bfloat16(acc.x), hy = __float2bfloat16(acc.y);
    __nv_bfloat16 hz = __float2bfloat16(acc.z), hw = __float2bfloat16(acc.w);
    __nv_bfloat162 hp0; hp0.x = hx; hp0.y = hy;
    __nv_bfloat162 hp1; hp1.x = hz; hp1.y = hw;
    __nv_bfloat162 lp0; lp0.x = __float2bfloat16(acc.x - __bfloat162float(hx));
                        lp0.y = __float2bfloat16(acc.y - __bfloat162float(hy));
    __nv_bfloat162 lp1; lp1.x = __float2bfloat16(acc.z - __bfloat162float(hz));
                        lp1.y = __float2bfloat16(acc.w - __bfloat162float(hw));
    uint2 hv; hv.x = *(uint32_t*)&hp0; hv.y = *(uint32_t*)&hp1;
    uint2 lv; lv.x = *(uint32_t*)&lp0; lv.y = *(uint32_t*)&lp1;
    *(uint2*)(Ohi + (size_t)gw * 128 + lane * 4) = hv;
    *(uint2*)(Olo + (size_t)gw * 128 + lane * 4) = lv;
}

// ================= weight fp32 -> transposed bf16 hi/lo =================
__global__ void convw_kernel(const float* __restrict__ W,
                             __nv_bfloat16* __restrict__ Whi,
                             __nv_bfloat16* __restrict__ Wlo) {
    int k = blockIdx.x, n = threadIdx.x;   // W[k][n] row-major [128,128]
    float v = W[k * 128 + n];
    __nv_bfloat16 h = __float2bfloat16(v);
    Whi[n * 128 + k] = h;                  // B[n][k] = W[k][n]
    Wlo[n * 128 + k] = __float2bfloat16(v - __bfloat162float(h));
}

// ================= HMMA GEMM: C = relu(A[128tile,128] @ W + b) =================
// mma.sync.m16n8k16 bf16, fp32 accum, 3-term hi/lo split.
// MODE 0: output split bf16 hi/lo   MODE 1: output fp32   MODE 2: fused mean-pool
#define SA 136                       // padded smem row stride (elements)
static constexpr int OFF_ALO  = 34816;
static constexpr int OFF_WHI  = 69632;
static constexpr int OFF_WLO  = 104448;
static constexpr int OFF_BIAS = 139264;
static constexpr int OFF_BATCH= 139776;
static constexpr int GEMM_SMEM= 140288;

__device__ __forceinline__ void mma16816(float* c,
    uint32_t a0, uint32_t a1, uint32_t a2, uint32_t a3, uint32_t b0, uint32_t b1) {
    asm volatile(
        "mma.sync.aligned.m16n8k16.row.col.f32.bf16.bf16.f32 "
        "{%0,%1,%2,%3}, {%4,%5,%6,%7}, {%8,%9}, {%0,%1,%2,%3};"
        : "+f"(c[0]), "+f"(c[1]), "+f"(c[2]), "+f"(c[3])
        : "r"(a0), "r"(a1), "r"(a2), "r"(a3), "r"(b0), "r"(b1));
}

template <int MODE>
__global__ void __launch_bounds__(512) gemm_mma(
    const __nv_bfloat16* __restrict__ Ahi, const __nv_bfloat16* __restrict__ Alo,
    const __nv_bfloat16* __restrict__ Whi, const __nv_bfloat16* __restrict__ Wlo,
    const float* __restrict__ bias,
    __nv_bfloat16* __restrict__ Ohi, __nv_bfloat16* __restrict__ Olo,
    float* __restrict__ Of32,
    const int* __restrict__ batch)
{
    extern __shared__ char sh[];
    __nv_bfloat16* sAhi = (__nv_bfloat16*)(sh);
    __nv_bfloat16* sAlo = (__nv_bfloat16*)(sh + OFF_ALO);
    __nv_bfloat16* sWhi = (__nv_bfloat16*)(sh + OFF_WHI);
    __nv_bfloat16* sWlo = (__nv_bfloat16*)(sh + OFF_WLO);
    float* sbias  = (float*)(sh + OFF_BIAS);
    int*   sbatch = (int*)(sh + OFF_BATCH);

    int tid = threadIdx.x;
    int row0 = blockIdx.x * 128;
    int nr = min(128, N_NODES - row0);

    if (tid < 128) {
        sbias[tid] = bias[tid];
        if (MODE == 2) sbatch[tid] = (tid < nr) ? batch[row0 + tid] : -1;
    }

    // ---- stage tiles (A guarded, W full) ----
    const uint4 z = make_uint4(0, 0, 0, 0);
    #pragma unroll
    for (int t = 0; t < 4; t++) {
        int idx = tid + t * 512;          // 0..2047
        int r = idx >> 4, c = idx & 15;   // 16 uint4 per 128-elem row
        uint4 vh, vl;
        if (r < nr) {
            vh = *(const uint4*)(Ahi + (size_t)(row0 + r) * 128 + c * 8);
            vl = *(const uint4*)(Alo + (size_t)(row0 + r) * 128 + c * 8);
        } else { vh = z; vl = z; }
        *(uint4*)(sAhi + r * SA + c * 8) = vh;
        *(uint4*)(sAlo + r * SA + c * 8) = vl;
        uint4 wh = *(const uint4*)(Whi + (size_t)r * 128 + c * 8);
        uint4 wl = *(const uint4*)(Wlo + (size_t)r * 128 + c * 8);
        *(uint4*)(sWhi + r * SA + c * 8) = wh;
        *(uint4*)(sWlo + r * SA + c * 8) = wl;
    }
    __syncthreads();

    int wid = tid >> 5, lid = tid & 31;
    int warp_m = wid >> 2, warp_n = wid & 3;   // 4x4 warp grid, warp tile 32x32
    int gid = lid >> 2, tig = lid & 3;

    float acc[2][4][4];
    #pragma unroll
    for (int ma = 0; ma < 2; ma++)
        #pragma unroll
        for (int nb = 0; nb < 4; nb++)
            #pragma unroll
            for (int q = 0; q < 4; q++) acc[ma][nb][q] = 0.0f;

    int aBase = (warp_m * 32 + gid) * SA + tig * 2;
    int bBase = (warp_n * 32 + gid) * SA + tig * 2;

    #pragma unroll
    for (int kk = 0; kk < 8; kk++) {
        int k0 = kk * 16;
        uint32_t ah[2][4], al[2][4];
        #pragma unroll
        for (int ma = 0; ma < 2; ma++) {
            int b = aBase + ma * 16 * SA + k0;
            ah[ma][0] = *(const uint32_t*)(sAhi + b);
            ah[ma][1] = *(const uint32_t*)(sAhi + b + 8 * SA);
            ah[ma][2] = *(const uint32_t*)(sAhi + b + 8);
            ah[ma][3] = *(const uint32_t*)(sAhi + b + 8 * SA + 8);
            al[ma][0] = *(const uint32_t*)(sAlo + b);
            al[ma][1] = *(const uint32_t*)(sAlo + b + 8 * SA);
            al[ma][2] = *(const uint32_t*)(sAlo + b + 8);
            al[ma][3] = *(const uint32_t*)(sAlo + b + 8 * SA + 8);
        }
        uint32_t bh[4][2], bl[4][2];
        #pragma unroll
        for (int nb = 0; nb < 4; nb++) {
            int b = bBase + nb * 8 * SA + k0;
            bh[nb][0] = *(const uint32_t*)(sWhi + b);
            bh[nb][1] = *(const uint32_t*)(sWhi + b + 8);
            bl[nb][0] = *(const uint32_t*)(sWlo + b);
            bl[nb][1] = *(const uint32_t*)(sWlo + b + 8);
        }
        #pragma unroll
        for (int ma = 0; ma < 2; ma++)
            #pragma unroll
            for (int nb = 0; nb < 4; nb++) {
                mma16816(acc[ma][nb], ah[ma][0], ah[ma][1], ah[ma][2], ah[ma][3], bh[nb][0], bh[nb][1]);
                mma16816(acc[ma][nb], ah[ma][0], ah[ma][1], ah[ma][2], ah[ma][3], bl[nb][0], bl[nb][1]);
                mma16816(acc[ma][nb], al[ma][0], al[ma][1], al[ma][2], al[ma][3], bh[nb][0], bh[nb][1]);
            }
    }

    if (MODE == 2) __syncthreads();   // tiles dead; about to reuse smem for sF
    float* sF = (float*)sh;           // [128][132]

    #pragma unroll
    for (int ma = 0; ma < 2; ma++)
        #pragma unroll
        for (int nb = 0; nb < 4; nb++) {
            int col = warp_n * 32 + nb * 8 + tig * 2;
            float bs0 = sbias[col], bs1 = sbias[col + 1];
            int r1 = warp_m * 32 + ma * 16 + gid;
            int r2 = r1 + 8;
            float v0 = fmaxf(acc[ma][nb][0] + bs0, 0.0f);
            float v1 = fmaxf(acc[ma][nb][1] + bs1, 0.0f);
            float v2 = fmaxf(acc[ma][nb][2] + bs0, 0.0f);
            float v3 = fmaxf(acc[ma][nb][3] + bs1, 0.0f);
            if (MODE == 0) {
                if (r1 < nr) {
                    __nv_bfloat16 h0 = __float2bfloat16(v0), h1 = __float2bfloat16(v1);
                    __nv_bfloat162 hp; hp.x = h0; hp.y = h1;
                    __nv_bfloat162 lp;
                    lp.x = __float2bfloat16(v0 - __bfloat162float(h0));
                    lp.y = __float2bfloat16(v1 - __bfloat162float(h1));
                    *(uint32_t*)(Ohi + (size_t)(row0 + r1) * 128 + col) = *(uint32_t*)&hp;
                    *(uint32_t*)(Olo + (size_t)(row0 + r1) * 128 + col) = *(uint32_t*)&lp;
                }
                if (r2 < nr) {
                    __nv_bfloat16 h2 = __float2bfloat16(v2), h3 = __float2bfloat16(v3);
                    __nv_bfloat162 hp; hp.x = h2; hp.y = h3;
                    __nv_bfloat162 lp;
                    lp.x = __float2bfloat16(v2 - __bfloat162float(h2));
                    lp.y = __float2bfloat16(v3 - __bfloat162float(h3));
                    *(uint32_t*)(Ohi + (size_t)(row0 + r2) * 128 + col) = *(uint32_t*)&hp;
                    *(uint32_t*)(Olo + (size_t)(row0 + r2) * 128 + col) = *(uint32_t*)&lp;
                }
            } else if (MODE == 1) {
                if (r1 < nr) { float2 p; p.x = v0; p.y = v1;
                    *(float2*)(Of32 + (size_t)(row0 + r1) * 128 + col) = p; }
                if (r2 < nr) { float2 p; p.x = v2; p.y = v3;
                    *(float2*)(Of32 + (size_t)(row0 + r2) * 128 + col) = p; }
            } else {
                float2 p1; p1.x = v0; p1.y = v1;
                float2 p2; p2.x = v2; p2.y = v3;
                *(float2*)(sF + r1 * 132 + col) = p1;
                *(float2*)(sF + r2 * 132 + col) = p2;
            }
        }

    if (MODE == 2) {
        __syncthreads();
        // batch is sorted: few segments per tile; 4 threads per column, 32 rows each
        int col = tid & 127, q = tid >> 7;
        int rs = q * 32, re = min(rs + 32, nr);
        float a = 0.0f; int cur = -1;
        for (int r = rs; r < re; r++) {
            int g = sbatch[r];
            if (g != cur) {
                if (cur >= 0) atomicAdd(&g_pool[cur * HIDDEN + col], a);
                cur = g; a = 0.0f;
            }
            a += sF[r * 132 + col];
        }
        if (cur >= 0) atomicAdd(&g_pool[cur * HIDDEN + col], a);
    }
}

// ================= final FC (counts via binary search on sorted batch) =================
__global__ void fc_kernel(const int* __restrict__ batch, const float* __restrict__ Wfc,
                          const float* __restrict__ bfc, float* __restrict__ out) {
    int g = blockIdx.x * blockDim.x + threadIdx.x;
    if (g >= NUM_GRAPHS) return;
    int lo = 0, hi = N_NODES;
    while (lo < hi) { int m = (lo + hi) >> 1; if (batch[m] < g) lo = m + 1; else hi = m; }
    int lb = lo;
    hi = N_NODES;
    while (lo < hi) { int m = (lo + hi) >> 1; if (batch[m] <= g) lo = m + 1; else hi = m; }
    float inv = 1.0f / fmaxf((float)(lo - lb), 1.0f);
    float a0 = 0.0f, a1 = 0.0f;
    const float* row = &g_pool[g * HIDDEN];
    #pragma unroll 4
    for (int k = 0; k < HIDDEN; k++) {
        float v = row[k];
        a0 += v * Wfc[k * 2 + 0];
        a1 += v * Wfc[k * 2 + 1];
    }
    out[g * 2 + 0] = a0 * inv + bfc[0];
    out[g * 2 + 1] = a1 * inv + bfc[1];
}

// ================= launch =================
extern "C" void kernel_launch(void* const* d_in, const int* in_sizes, int n_in,
                              void* d_out, int out_size) {
    const float* x = nullptr;
    const int* ei = nullptr;
    const int* batch = nullptr;
    const float* Ws[4] = {nullptr, nullptr, nullptr, nullptr};
    const float* bs[4] = {nullptr, nullptr, nullptr, nullptr};
    const float* Wfc = nullptr;
    const float* bfc = nullptr;
    int wi = 0, bi = 0;
    for (int i = 0; i < n_in; i++) {
        int sz = in_sizes[i];
        if      (sz == N_NODES * HIDDEN)  x     = (const float*)d_in[i];
        else if (sz == 2 * N_EDGES)       ei    = (const int*)d_in[i];
        else if (sz == N_NODES)           batch = (const int*)d_in[i];
        else if (sz == HIDDEN * HIDDEN)   { if (wi < 4) Ws[wi++] = (const float*)d_in[i]; }
        else if (sz == HIDDEN)            { if (bi < 4) bs[bi++] = (const float*)d_in[i]; }
        else if (sz == HIDDEN * 2)        Wfc   = (const float*)d_in[i];
        else if (sz == 2)                 bfc   = (const float*)d_in[i];
    }
    float* out = (float*)d_out;

    __nv_bfloat16 *Ahi, *Alo, *Mhi, *Mlo, *Whi0, *Wlo0;
    float *H;
    cudaGetSymbolAddress((void**)&Ahi,  g_Ahi);
    cudaGetSymbolAddress((void**)&Alo,  g_Alo);
    cudaGetSymbolAddress((void**)&Mhi,  g_Mhi);
    cudaGetSymbolAddress((void**)&Mlo,  g_Mlo);
    cudaGetSymbolAddress((void**)&H,    g_H);
    cudaGetSymbolAddress((void**)&Whi0, g_Whi);
    cudaGetSymbolAddress((void**)&Wlo0, g_Wlo);

    cudaFuncSetAttribute(gemm_mma<0>, cudaFuncAttributeMaxDynamicSharedMemorySize, GEMM_SMEM);
    cudaFuncSetAttribute(gemm_mma<1>, cudaFuncAttributeMaxDynamicSharedMemorySize, GEMM_SMEM);
    cudaFuncSetAttribute(gemm_mma<2>, cudaFuncAttributeMaxDynamicSharedMemorySize, GEMM_SMEM);

    // CSR build + weight conversion + zero pool
    zero_kernel<<<256, 256>>>();
    for (int i = 0; i < 4; i++)
        convw_kernel<<<128, 128>>>(Ws[i], Whi0 + i * HIDDEN * HIDDEN, Wlo0 + i * HIDDEN * HIDDEN);
    hist_kernel<<<(N_EDGES + 255) / 256, 256>>>(ei);
    scan_kernel<<<1, 1024>>>();
    fill_kernel<<<(N_EDGES + 255) / 256, 256>>>(ei);

    int agg_blocks  = (N_NODES * 32 + 255) / 256;
    int gemm_blocks = (N_NODES + 127) / 128;

    // Layer 1
    agg_conv_kernel<<<agg_blocks, 256>>>((const float4*)x, Ahi, Alo);
    gemm_mma<0><<<gemm_blocks, 512, GEMM_SMEM>>>(Ahi, Alo, Whi0 + 0 * 16384, Wlo0 + 0 * 16384,
                                                 bs[0], Mhi, Mlo, nullptr, nullptr);
    gemm_mma<1><<<gemm_blocks, 512, GEMM_SMEM>>>(Mhi, Mlo, Whi0 + 1 * 16384, Wlo0 + 1 * 16384,
                                                 bs[1], nullptr, nullptr, H, nullptr);
    // Layer 2
    agg_conv_kernel<<<agg_blocks, 256>>>((const float4*)H, Ahi, Alo);
    gemm_mma<0><<<gemm_blocks, 512, GEMM_SMEM>>>(Ahi, Alo, Whi0 + 2 * 16384, Wlo0 + 2 * 16384,
                                                 bs[2], Mhi, Mlo, nullptr, nullptr);
    gemm_mma<2><<<gemm_blocks, 512, GEMM_SMEM>>>(Mhi, Mlo, Whi0 + 3 * 16384, Wlo0 + 3 * 16384,
                                                 bs[3], nullptr, nullptr, nullptr, batch);
    // FC
    fc_kernel<<<(NUM_GRAPHS + 255) / 256, 256>>>(batch, Wfc, bfc, out);
}